// round 14
// baseline (speedup 1.0000x reference)
#include <cuda_runtime.h>
#include <math.h>

#define OUTF 8192
#define INF_ 8192
#define NKCHUNKS 64
#define KCHUNK (INF_ / NKCHUNKS)          // 128
#define T1 256
#define COLS_PER_THREAD 4
#define COLBLOCKS 8                       // 8 * 64 = 512 blocks
#define NBLK (COLBLOCKS * NKCHUNKS)       // 512
#define DEPTH 8                           // cp.async slots (7 in flight)

// Scratch (no allocations allowed). Zero-initialized at module load; the
// finisher block restores everything to zero each launch -> deterministic
// graph replays.
__device__ float g_hW[4 * OUTF];
__device__ unsigned int g_counter;

__device__ __forceinline__ void red_add_v4(float* ptr, float4 v) {
    asm volatile("red.global.add.v4.f32 [%0], {%1, %2, %3, %4};"
                 :: "l"(ptr), "f"(v.x), "f"(v.y), "f"(v.z), "f"(v.w)
                 : "memory");
}

__device__ __forceinline__ void cp_async16(void* smem_dst, const void* gsrc) {
    unsigned int sa = (unsigned int)__cvta_generic_to_shared(smem_dst);
    asm volatile("cp.async.cg.shared.global [%0], [%1], 16;"
                 :: "r"(sa), "l"(gsrc) : "memory");
}
#define CP_COMMIT() asm volatile("cp.async.commit_group;" ::: "memory")
#define CP_WAIT(n)  asm volatile("cp.async.wait_group %0;" :: "n"(n) : "memory")

// ---------------------------------------------------------------------------
// Single kernel: cp.async-pipelined split-K GEMM (all blocks) -> last arriving
// block finishes distances -> softmax -> h_prime -> output, resets scratch.
// ---------------------------------------------------------------------------
__global__ void __launch_bounds__(T1, 4) gat_kernel(const float* __restrict__ h,
                                                    const int* __restrict__ adj,
                                                    const float* __restrict__ W,
                                                    float* __restrict__ out,
                                                    int out_size) {
    __shared__ float4 wbuf[DEPTH][T1];    // 32 KB streaming buffer
    __shared__ float4 hst[KCHUNK];        // 2 KB: packed h (4 rows per float4)
    __shared__ float red_s[6][8];
    __shared__ float att_s[9];
    __shared__ int s_last;
    const int tid = threadIdx.x;
    const int b   = blockIdx.x;

    // ===== Phase 1: split-K GEMM, cp.async pipeline, RED.v4 accumulate ======
    {
        const int colblock = b & (COLBLOCKS - 1);
        const int kchunk   = b >> 3;
        const int k0 = kchunk * KCHUNK;
        const int col = (colblock * T1 + tid) * COLS_PER_THREAD;

        // this thread's W column strip: 16B per row, row stride OUTF floats
        const float* wp = W + (size_t)k0 * OUTF + col;

        // pack h chunk: hst[kk] = {h0[kk], h1[kk], h2[kk], h3[kk]}
        if (tid < KCHUNK) {
            float4 hv;
            hv.x = h[0 * INF_ + k0 + tid];
            hv.y = h[1 * INF_ + k0 + tid];
            hv.z = h[2 * INF_ + k0 + tid];
            hv.w = h[3 * INF_ + k0 + tid];
            hst[tid] = hv;
        }

        // prologue: 7 rows in flight
#pragma unroll
        for (int r = 0; r < DEPTH - 1; r++) {
            cp_async16(&wbuf[r][tid], wp + (size_t)r * OUTF);
            CP_COMMIT();
        }
        __syncthreads();   // hst ready (placed after prologue to overlap)

        float4 a0 = make_float4(0.f, 0.f, 0.f, 0.f);
        float4 a1 = make_float4(0.f, 0.f, 0.f, 0.f);
        float4 a2 = make_float4(0.f, 0.f, 0.f, 0.f);
        float4 a3 = make_float4(0.f, 0.f, 0.f, 0.f);

#pragma unroll 4
        for (int r = 0; r < KCHUNK; r++) {
            CP_WAIT(DEPTH - 2);                 // row r's 16B has landed
            float4 w  = wbuf[r & (DEPTH - 1)][tid];
            int nr = r + DEPTH - 1;
            if (nr < KCHUNK)                    // prefetch into slot read last iter
                cp_async16(&wbuf[nr & (DEPTH - 1)][tid], wp + (size_t)nr * OUTF);
            CP_COMMIT();
            float4 hv = hst[r];                 // broadcast LDS.128
            a0.x += hv.x * w.x; a0.y += hv.x * w.y; a0.z += hv.x * w.z; a0.w += hv.x * w.w;
            a1.x += hv.y * w.x; a1.y += hv.y * w.y; a1.z += hv.y * w.z; a1.w += hv.y * w.w;
            a2.x += hv.z * w.x; a2.y += hv.z * w.y; a2.z += hv.z * w.z; a2.w += hv.z * w.w;
            a3.x += hv.w * w.x; a3.y += hv.w * w.y; a3.z += hv.w * w.z; a3.w += hv.w * w.w;
        }

        red_add_v4(&g_hW[0 * OUTF + col], a0);
        red_add_v4(&g_hW[1 * OUTF + col], a1);
        red_add_v4(&g_hW[2 * OUTF + col], a2);
        red_add_v4(&g_hW[3 * OUTF + col], a3);
    }

    // ===== Arrival counter: only the 512th arriver continues ================
    __threadfence();                    // publish this block's RED ops
    __syncthreads();
    if (tid == 0) {
        unsigned int old = atomicAdd(&g_counter, 1u);
        s_last = (old == NBLK - 1u) ? 1 : 0;
    }
    __syncthreads();
    if (!s_last) return;
    __threadfence();                    // acquire: all blocks' REDs visible

    // ===== Phase 2: squared distances (256 threads, 8 iters each) ===========
    {
        float s01 = 0.f, s02 = 0.f, s03 = 0.f, s12 = 0.f, s13 = 0.f, s23 = 0.f;
        const float4* hw = (const float4*)g_hW;
        const int N4 = OUTF / 4;
#pragma unroll
        for (int it = 0; it < N4 / T1; it++) {
            int c = it * T1 + tid;
            float4 x0 = hw[0 * N4 + c];
            float4 x1 = hw[1 * N4 + c];
            float4 x2 = hw[2 * N4 + c];
            float4 x3 = hw[3 * N4 + c];
            float d;
            d = x0.x - x1.x; s01 += d * d; d = x0.y - x1.y; s01 += d * d;
            d = x0.z - x1.z; s01 += d * d; d = x0.w - x1.w; s01 += d * d;
            d = x0.x - x2.x; s02 += d * d; d = x0.y - x2.y; s02 += d * d;
            d = x0.z - x2.z; s02 += d * d; d = x0.w - x2.w; s02 += d * d;
            d = x0.x - x3.x; s03 += d * d; d = x0.y - x3.y; s03 += d * d;
            d = x0.z - x3.z; s03 += d * d; d = x0.w - x3.w; s03 += d * d;
            d = x1.x - x2.x; s12 += d * d; d = x1.y - x2.y; s12 += d * d;
            d = x1.z - x2.z; s12 += d * d; d = x1.w - x2.w; s12 += d * d;
            d = x1.x - x3.x; s13 += d * d; d = x1.y - x3.y; s13 += d * d;
            d = x1.z - x3.z; s13 += d * d; d = x1.w - x3.w; s13 += d * d;
            d = x2.x - x3.x; s23 += d * d; d = x2.y - x3.y; s23 += d * d;
            d = x2.z - x3.z; s23 += d * d; d = x2.w - x3.w; s23 += d * d;
        }
#pragma unroll
        for (int off = 16; off > 0; off >>= 1) {
            s01 += __shfl_down_sync(0xffffffffu, s01, off);
            s02 += __shfl_down_sync(0xffffffffu, s02, off);
            s03 += __shfl_down_sync(0xffffffffu, s03, off);
            s12 += __shfl_down_sync(0xffffffffu, s12, off);
            s13 += __shfl_down_sync(0xffffffffu, s13, off);
            s23 += __shfl_down_sync(0xffffffffu, s23, off);
        }
        int w = tid >> 5, l = tid & 31;
        if (l == 0) {
            red_s[0][w] = s01; red_s[1][w] = s02; red_s[2][w] = s03;
            red_s[3][w] = s12; red_s[4][w] = s13; red_s[5][w] = s23;
        }
    }
    __syncthreads();

    // ===== Phase 3: attention softmax (thread 0) ============================
    if (tid == 0) {
        float t[6];
        for (int j = 0; j < 6; j++) {
            float s = 0.f;
            for (int i = 0; i < 8; i++) s += red_s[j][i];
            t[j] = s;
        }
        // zero-safe sqrt (matches reference _cdist)
        float d01 = (t[0] > 0.f) ? sqrtf(t[0]) : 0.f;
        float d02 = (t[1] > 0.f) ? sqrtf(t[1]) : 0.f;
        float d03 = (t[2] > 0.f) ? sqrtf(t[2]) : 0.f;
        float d12 = (t[3] > 0.f) ? sqrtf(t[3]) : 0.f;
        float d13 = (t[4] > 0.f) ? sqrtf(t[4]) : 0.f;
        float d23 = (t[5] > 0.f) ? sqrtf(t[5]) : 0.f;
        // leaky_relu is identity for x >= 0 (distances nonnegative)
        float v01 = d12 + 0.5f * (d01 + d02);
        float v02 = d13 + 0.5f * (d01 + d03);
        float v12 = d23 + 0.5f * (d02 + d03);

        float e[3][3] = {{0.f, v01, v02},
                         {v01, 0.f, v12},
                         {v02, v12, 0.f}};

        for (int j = 0; j < 3; j++) {
            float c[3];
            for (int i = 0; i < 3; i++)
                c[i] = (adj[i * 3 + j] > 0) ? e[i][j] : -9e15f;
            float mx = fmaxf(c[0], fmaxf(c[1], c[2]));
            float ex0 = expf(c[0] - mx);
            float ex1 = expf(c[1] - mx);
            float ex2 = expf(c[2] - mx);
            float inv = 1.0f / (ex0 + ex1 + ex2);
            att_s[0 * 3 + j] = ex0 * inv;
            att_s[1 * 3 + j] = ex1 * inv;
            att_s[2 * 3 + j] = ex2 * inv;
        }
        out[out_size - 3] = v01;
        out[out_size - 2] = v02;
        out[out_size - 1] = v12;
    }
    __syncthreads();

    // ===== Phase 4: h_prime + output + zero scratch =========================
    {
        const float a00 = att_s[0], a01 = att_s[1], a02 = att_s[2];
        const float a10 = att_s[3], a11 = att_s[4], a12 = att_s[5];
        const float a20 = att_s[6], a21 = att_s[7], a22 = att_s[8];
        const float4* hw = (const float4*)g_hW;
        float4* hwm = (float4*)g_hW;
        float4* o = (float4*)out;
        const int N4 = OUTF / 4;
        const float4 z = make_float4(0.f, 0.f, 0.f, 0.f);

#pragma unroll
        for (int it = 0; it < N4 / T1; it++) {
            int c = it * T1 + tid;
            float4 r0 = hw[0 * N4 + c];      // L1 hits (read in phase 2)
            float4 b0 = hw[1 * N4 + c];
            float4 b1 = hw[2 * N4 + c];
            float4 b2 = hw[3 * N4 + c];

            o[c] = r0;
            float4 r;
            r.x = a00 * b0.x + a01 * b1.x + a02 * b2.x;
            r.y = a00 * b0.y + a01 * b1.y + a02 * b2.y;
            r.z = a00 * b0.z + a01 * b1.z + a02 * b2.z;
            r.w = a00 * b0.w + a01 * b1.w + a02 * b2.w;
            o[1 * N4 + c] = r;
            r.x = a10 * b0.x + a11 * b1.x + a12 * b2.x;
            r.y = a10 * b0.y + a11 * b1.y + a12 * b2.y;
            r.z = a10 * b0.z + a11 * b1.z + a12 * b2.z;
            r.w = a10 * b0.w + a11 * b1.w + a12 * b2.w;
            o[2 * N4 + c] = r;
            r.x = a20 * b0.x + a21 * b1.x + a22 * b2.x;
            r.y = a20 * b0.y + a21 * b1.y + a22 * b2.y;
            r.z = a20 * b0.z + a21 * b1.z + a22 * b2.z;
            r.w = a20 * b0.w + a21 * b1.w + a22 * b2.w;
            o[3 * N4 + c] = r;

            // restore scratch to zero for the next (graph-replayed) launch
            hwm[0 * N4 + c] = z;
            hwm[1 * N4 + c] = z;
            hwm[2 * N4 + c] = z;
            hwm[3 * N4 + c] = z;
        }
    }
    __syncthreads();
    if (tid == 0) g_counter = 0u;           // only this block is still alive
}

// ---------------------------------------------------------------------------
extern "C" void kernel_launch(void* const* d_in, const int* in_sizes, int n_in,
                              void* d_out, int out_size) {
    const float* h   = (const float*)d_in[0];   // [4, 8192]
    const int*   adj = (const int*)d_in[1];     // [3, 3]
    const float* W   = (const float*)d_in[2];   // [8192, 8192]
    float* out = (float*)d_out;

    gat_kernel<<<NBLK, T1>>>(h, adj, W, out, out_size);
}